// round 3
// baseline (speedup 1.0000x reference)
#include <cuda_runtime.h>

// HairBundle SDE drift + constant diffusion. Streaming, memory-bound.
// Traffic floor: 160MB read + 320MB write = 480MB -> ~60us @ 8TB/s.
// R1: 4 rows/thread, DRAM=54.7%, 98us -> latency/MLP bound.
// R2: 8 rows/thread (MLP_p1=10), __ldcs/__stcs streaming hints, occ pinned.

__device__ __forceinline__ void hb_row(float x_hb, float x_a, float p_m,
                                       float p_gs, float p_t, float force,
                                       float* __restrict__ o) {
    float z    = 4.0f * (x_hb - x_a);                 // (x_hb - x_a)/DELTA
    float p_o  = 1.0f / (1.0f + __expf(-z));          // sigmoid
    float f_gs = 0.75f * (x_hb - x_a - 0.5f * p_o);
    o[0] = -f_gs - 0.6f * x_hb + force;
    o[1] = 0.1f * (f_gs - 0.45f * x_a - 0.35f * (1.0f - 0.9f * p_m));
    o[2] = 1.2f * p_o * (1.0f - p_m)  - 0.8f * p_m;
    o[3] = 0.7f * p_o * (1.0f - p_gs) - 0.5f * p_gs;
    o[4] = 0.3f * p_o * (1.0f - p_t)  - 0.4f * p_t;
}

// Each thread: 8 rows = 40 floats = 10 x float4 loads (front-batched),
// then two quad-halves of compute+store to bound live registers.
__global__ __launch_bounds__(256, 4)
void hb_oct_kernel(const float* __restrict__ t,
                   const float* __restrict__ x,
                   float* __restrict__ drift,
                   float* __restrict__ diffu,
                   int nocts) {
    int i = blockIdx.x * blockDim.x + threadIdx.x;
    if (i >= nocts) return;

    float force = 0.5f * __sinf(6.283185307179586f * t[0]);

    const float4* __restrict__ xin = reinterpret_cast<const float4*>(x) + (size_t)i * 10;
    // Front-batch all 10 loads: MLP_p1 = 10.
    float4 v0 = __ldcs(xin + 0), v1 = __ldcs(xin + 1), v2 = __ldcs(xin + 2),
           v3 = __ldcs(xin + 3), v4 = __ldcs(xin + 4), v5 = __ldcs(xin + 5),
           v6 = __ldcs(xin + 6), v7 = __ldcs(xin + 7), v8 = __ldcs(xin + 8),
           v9 = __ldcs(xin + 9);

    float4* __restrict__ dout = reinterpret_cast<float4*>(drift) + (size_t)i * 10;
    float4* __restrict__ gout = reinterpret_cast<float4*>(diffu) + (size_t)i * 10;

    // ---- half 0: rows 0-3 from v0..v4 ----
    {
        float o[20];
        hb_row(v0.x, v0.y, v0.z, v0.w, v1.x, force, o + 0);
        hb_row(v1.y, v1.z, v1.w, v2.x, v2.y, force, o + 5);
        hb_row(v2.z, v2.w, v3.x, v3.y, v3.z, force, o + 10);
        hb_row(v3.w, v4.x, v4.y, v4.z, v4.w, force, o + 15);
        __stcs(dout + 0, make_float4(o[0],  o[1],  o[2],  o[3]));
        __stcs(dout + 1, make_float4(o[4],  o[5],  o[6],  o[7]));
        __stcs(dout + 2, make_float4(o[8],  o[9],  o[10], o[11]));
        __stcs(dout + 3, make_float4(o[12], o[13], o[14], o[15]));
        __stcs(dout + 4, make_float4(o[16], o[17], o[18], o[19]));
    }
    // ---- half 1: rows 4-7 from v5..v9 ----
    {
        float o[20];
        hb_row(v5.x, v5.y, v5.z, v5.w, v6.x, force, o + 0);
        hb_row(v6.y, v6.z, v6.w, v7.x, v7.y, force, o + 5);
        hb_row(v7.z, v7.w, v8.x, v8.y, v8.z, force, o + 10);
        hb_row(v8.w, v9.x, v9.y, v9.z, v9.w, force, o + 15);
        __stcs(dout + 5, make_float4(o[0],  o[1],  o[2],  o[3]));
        __stcs(dout + 6, make_float4(o[4],  o[5],  o[6],  o[7]));
        __stcs(dout + 7, make_float4(o[8],  o[9],  o[10], o[11]));
        __stcs(dout + 8, make_float4(o[12], o[13], o[14], o[15]));
        __stcs(dout + 9, make_float4(o[16], o[17], o[18], o[19]));
    }

    // diffusion: constant tile [0.05, 0.02, 0, 0, 0] over 40 floats (period 20)
    __stcs(gout + 0, make_float4(0.05f, 0.02f, 0.0f,  0.0f));
    __stcs(gout + 1, make_float4(0.0f,  0.05f, 0.02f, 0.0f));
    __stcs(gout + 2, make_float4(0.0f,  0.0f,  0.05f, 0.02f));
    __stcs(gout + 3, make_float4(0.0f,  0.0f,  0.0f,  0.05f));
    __stcs(gout + 4, make_float4(0.02f, 0.0f,  0.0f,  0.0f));
    __stcs(gout + 5, make_float4(0.05f, 0.02f, 0.0f,  0.0f));
    __stcs(gout + 6, make_float4(0.0f,  0.05f, 0.02f, 0.0f));
    __stcs(gout + 7, make_float4(0.0f,  0.0f,  0.05f, 0.02f));
    __stcs(gout + 8, make_float4(0.0f,  0.0f,  0.0f,  0.05f));
    __stcs(gout + 9, make_float4(0.02f, 0.0f,  0.0f,  0.0f));
}

// Scalar tail for B % 8 != 0 (not hit for B=8M, kept for safety).
__global__ void hb_tail_kernel(const float* __restrict__ t,
                               const float* __restrict__ x,
                               float* __restrict__ drift,
                               float* __restrict__ diffu,
                               int row0, int nrows) {
    int r = row0 + blockIdx.x * blockDim.x + threadIdx.x;
    if (r >= row0 + nrows) return;
    float force = 0.5f * __sinf(6.283185307179586f * t[0]);
    const float* xr = x + (size_t)r * 5;
    float o[5];
    hb_row(xr[0], xr[1], xr[2], xr[3], xr[4], force, o);
    float* dr = drift + (size_t)r * 5;
    float* gr = diffu + (size_t)r * 5;
    dr[0] = o[0]; dr[1] = o[1]; dr[2] = o[2]; dr[3] = o[3]; dr[4] = o[4];
    gr[0] = 0.05f; gr[1] = 0.02f; gr[2] = 0.0f; gr[3] = 0.0f; gr[4] = 0.0f;
}

extern "C" void kernel_launch(void* const* d_in, const int* in_sizes, int n_in,
                              void* d_out, int out_size) {
    const float* t = (const float*)d_in[0];   // [1]
    const float* x = (const float*)d_in[1];   // [B*5]
    float* out   = (float*)d_out;
    int B        = in_sizes[1] / 5;
    float* drift = out;                        // first half
    float* diffu = out + (size_t)out_size / 2; // second half

    int nocts = B / 8;
    int rem   = B - nocts * 8;

    const int TPB = 256;
    if (nocts > 0) {
        int blocks = (nocts + TPB - 1) / TPB;
        hb_oct_kernel<<<blocks, TPB>>>(t, x, drift, diffu, nocts);
    }
    if (rem > 0) {
        hb_tail_kernel<<<1, 64>>>(t, x, drift, diffu, nocts * 8, rem);
    }
}

// round 5
// speedup vs baseline: 1.8454x; 1.8454x over previous
#include <cuda_runtime.h>

// HairBundle SDE drift + constant diffusion. Streaming, memory-bound.
// Floor: 160MB read + 320MB write = 480MB -> ~60us @ 8TB/s.
// R1: 4 rows/thread strided float4 (20 lines/warp-instr) -> L1-queue bound, 98us.
// R2: 8 rows/thread -> worse (occ + MLP down), 162us.
// R3: smem-staged coalesced global access (4 lines/warp-instr), compute from smem.

#define TPB 256
#define F4_PER_BLOCK (TPB * 5)      // 1280 float4 = 1024 rows = 20KB
#define ROWS_PER_BLOCK (TPB * 4)

__device__ __forceinline__ void hb_row(float x_hb, float x_a, float p_m,
                                       float p_gs, float p_t, float force,
                                       float* __restrict__ o) {
    float z    = 4.0f * (x_hb - x_a);                 // (x_hb - x_a)/DELTA
    float p_o  = 1.0f / (1.0f + __expf(-z));          // sigmoid
    float f_gs = 0.75f * (x_hb - x_a - 0.5f * p_o);
    o[0] = -f_gs - 0.6f * x_hb + force;
    o[1] = 0.1f * (f_gs - 0.45f * x_a - 0.35f * (1.0f - 0.9f * p_m));
    o[2] = 1.2f * p_o * (1.0f - p_m)  - 0.8f * p_m;
    o[3] = 0.7f * p_o * (1.0f - p_gs) - 0.5f * p_gs;
    o[4] = 0.3f * p_o * (1.0f - p_t)  - 0.4f * p_t;
}

__global__ __launch_bounds__(TPB)
void hb_coalesced_kernel(const float* __restrict__ t,
                         const float4* __restrict__ x4,
                         float4* __restrict__ drift4,
                         float4* __restrict__ diffu4,
                         int B, int nf4) {
    __shared__ float4 buf[F4_PER_BLOCK];
    const int tid  = threadIdx.x;
    const int base = blockIdx.x * F4_PER_BLOCK;   // f4 index; nf4 = 10M fits int

    float force = 0.5f * __sinf(6.283185307179586f * t[0]);

    // ---- stage input: fully coalesced LDG.128 ----
    #pragma unroll
    for (int k = 0; k < 5; k++) {
        int g = base + tid + k * TPB;
        if (g < nf4) buf[tid + k * TPB] = x4[g];
    }
    __syncthreads();

    // ---- compute 4 rows from smem, write drift back to same slots ----
    int row0 = blockIdx.x * ROWS_PER_BLOCK + tid * 4;
    if (row0 < B) {
        float4 a = buf[tid * 5 + 0];
        float4 b = buf[tid * 5 + 1];
        float4 c = buf[tid * 5 + 2];
        float4 d = buf[tid * 5 + 3];
        float4 e = buf[tid * 5 + 4];
        float o[20];
        hb_row(a.x, a.y, a.z, a.w, b.x, force, o + 0);
        hb_row(b.y, b.z, b.w, c.x, c.y, force, o + 5);
        hb_row(c.z, c.w, d.x, d.y, d.z, force, o + 10);
        hb_row(d.w, e.x, e.y, e.z, e.w, force, o + 15);
        buf[tid * 5 + 0] = make_float4(o[0],  o[1],  o[2],  o[3]);
        buf[tid * 5 + 1] = make_float4(o[4],  o[5],  o[6],  o[7]);
        buf[tid * 5 + 2] = make_float4(o[8],  o[9],  o[10], o[11]);
        buf[tid * 5 + 3] = make_float4(o[12], o[13], o[14], o[15]);
        buf[tid * 5 + 4] = make_float4(o[16], o[17], o[18], o[19]);
    }
    __syncthreads();

    // ---- stream drift out: fully coalesced STG.128 ----
    #pragma unroll
    for (int k = 0; k < 5; k++) {
        int g = base + tid + k * TPB;
        if (g < nf4) drift4[g] = buf[tid + k * TPB];
    }

    // ---- diffusion: constant period-5 float4 pattern, coalesced, no smem ----
    // base % 5 == 0 (1280 % 5 == 0), so pattern idx = (tid%5 + k) % 5.
    int m = tid % 5;
    #pragma unroll
    for (int k = 0; k < 5; k++) {
        int g = base + tid + k * TPB;
        int p = m + k; if (p >= 5) p -= 5;
        float4 v = (p == 0) ? make_float4(0.05f, 0.02f, 0.0f,  0.0f)  :
                   (p == 1) ? make_float4(0.0f,  0.05f, 0.02f, 0.0f)  :
                   (p == 2) ? make_float4(0.0f,  0.0f,  0.05f, 0.02f) :
                   (p == 3) ? make_float4(0.0f,  0.0f,  0.0f,  0.05f) :
                              make_float4(0.02f, 0.0f,  0.0f,  0.0f);
        if (g < nf4) diffu4[g] = v;
    }
}

extern "C" void kernel_launch(void* const* d_in, const int* in_sizes, int n_in,
                              void* d_out, int out_size) {
    const float* t  = (const float*)d_in[0];   // [1]
    const float* x  = (const float*)d_in[1];   // [B*5], B*5 % 4 == 0 (B=8M)
    float* out      = (float*)d_out;
    int B           = in_sizes[1] / 5;
    int nf4         = in_sizes[1] / 4;         // 10,000,000 for B=8M
    float4* drift4  = (float4*)out;
    float4* diffu4  = (float4*)(out + (size_t)out_size / 2);

    int nblocks = (nf4 + F4_PER_BLOCK - 1) / F4_PER_BLOCK;  // 7813
    hb_coalesced_kernel<<<nblocks, TPB>>>(t, (const float4*)x, drift4, diffu4, B, nf4);
}

// round 6
// speedup vs baseline: 2.1532x; 1.1668x over previous
#include <cuda_runtime.h>

// HairBundle SDE drift + constant diffusion. Streaming, memory-bound.
// Floor: 160MB read + 320MB write = 480MB -> ~65us @ ~7.4TB/s achievable.
// R1: strided float4, L1-queue bound, 98us. R2: 8 rows/thread, 162us (worse).
// R3: smem-staged coalesced, 88.6us (DRAM 59.8%, issue 45%).
// R4: no predication (tail kernel), diffusion stores overlap LDG window,
//     __stcs write-streaming, launch_bounds(256,6) for 48 warps/SM.

#define TPB 256
#define F4_PER_BLOCK (TPB * 5)      // 1280 float4 = 1024 rows = 20KB
#define ROWS_PER_BLOCK (TPB * 4)

__device__ __forceinline__ void hb_row(float x_hb, float x_a, float p_m,
                                       float p_gs, float p_t, float force,
                                       float* __restrict__ o) {
    float z    = 4.0f * (x_hb - x_a);                 // (x_hb - x_a)/DELTA
    float p_o  = 1.0f / (1.0f + __expf(-z));          // sigmoid
    float f_gs = 0.75f * (x_hb - x_a - 0.5f * p_o);
    o[0] = -f_gs - 0.6f * x_hb + force;
    o[1] = 0.1f * (f_gs - 0.45f * x_a - 0.35f * (1.0f - 0.9f * p_m));
    o[2] = 1.2f * p_o * (1.0f - p_m)  - 0.8f * p_m;
    o[3] = 0.7f * p_o * (1.0f - p_gs) - 0.5f * p_gs;
    o[4] = 0.3f * p_o * (1.0f - p_t)  - 0.4f * p_t;
}

__global__ __launch_bounds__(TPB, 6)
void hb_main_kernel(const float* __restrict__ t,
                    const float4* __restrict__ x4,
                    float4* __restrict__ drift4,
                    float4* __restrict__ diffu4) {
    __shared__ float4 buf[F4_PER_BLOCK];
    const int tid  = threadIdx.x;
    const int base = blockIdx.x * F4_PER_BLOCK;

    float force = 0.5f * __sinf(6.283185307179586f * t[0]);

    // ---- stage input: fully coalesced LDG.128, no predication ----
    float4 s0 = x4[base + tid + 0 * TPB];
    float4 s1 = x4[base + tid + 1 * TPB];
    float4 s2 = x4[base + tid + 2 * TPB];
    float4 s3 = x4[base + tid + 3 * TPB];
    float4 s4 = x4[base + tid + 4 * TPB];

    // ---- diffusion stores: dependency-free, fill the LDG-latency window ----
    // base % 5 == 0, so pattern index = (tid%5 + k) % 5 for k-th chunk.
    {
        int m = tid % 5;
        #pragma unroll
        for (int k = 0; k < 5; k++) {
            int p = m + k; if (p >= 5) p -= 5;
            float4 v = (p == 0) ? make_float4(0.05f, 0.02f, 0.0f,  0.0f)  :
                       (p == 1) ? make_float4(0.0f,  0.05f, 0.02f, 0.0f)  :
                       (p == 2) ? make_float4(0.0f,  0.0f,  0.05f, 0.02f) :
                       (p == 3) ? make_float4(0.0f,  0.0f,  0.0f,  0.05f) :
                                  make_float4(0.02f, 0.0f,  0.0f,  0.0f);
            __stcs(diffu4 + base + tid + k * TPB, v);
        }
    }

    buf[tid + 0 * TPB] = s0;
    buf[tid + 1 * TPB] = s1;
    buf[tid + 2 * TPB] = s2;
    buf[tid + 3 * TPB] = s3;
    buf[tid + 4 * TPB] = s4;
    __syncthreads();

    // ---- compute 4 rows; sliding-window register use, write back in place ----
    {
        const int i5 = tid * 5;
        float4 a = buf[i5 + 0];
        float4 b = buf[i5 + 1];
        float o0[5], o1[5];
        hb_row(a.x, a.y, a.z, a.w, b.x, force, o0);          // row 0
        float4 c = buf[i5 + 2];
        hb_row(b.y, b.z, b.w, c.x, c.y, force, o1);          // row 1
        buf[i5 + 0] = make_float4(o0[0], o0[1], o0[2], o0[3]);
        buf[i5 + 1] = make_float4(o0[4], o1[0], o1[1], o1[2]);
        float4 d = buf[i5 + 3];
        float o2[5];
        hb_row(c.z, c.w, d.x, d.y, d.z, force, o2);          // row 2
        buf[i5 + 2] = make_float4(o1[3], o1[4], o2[0], o2[1]);
        float4 e = buf[i5 + 4];
        float o3[5];
        hb_row(d.w, e.x, e.y, e.z, e.w, force, o3);          // row 3
        buf[i5 + 3] = make_float4(o2[2], o2[3], o2[4], o3[0]);
        buf[i5 + 4] = make_float4(o3[1], o3[2], o3[3], o3[4]);
    }
    __syncthreads();

    // ---- stream drift out: fully coalesced STG.128, write-streaming ----
    __stcs(drift4 + base + tid + 0 * TPB, buf[tid + 0 * TPB]);
    __stcs(drift4 + base + tid + 1 * TPB, buf[tid + 1 * TPB]);
    __stcs(drift4 + base + tid + 2 * TPB, buf[tid + 2 * TPB]);
    __stcs(drift4 + base + tid + 3 * TPB, buf[tid + 3 * TPB]);
    __stcs(drift4 + base + tid + 4 * TPB, buf[tid + 4 * TPB]);
}

// Tail: remaining rows handled scalar per-row (tiny, latency-irrelevant).
__global__ void hb_tail_kernel(const float* __restrict__ t,
                               const float* __restrict__ x,
                               float* __restrict__ drift,
                               float* __restrict__ diffu,
                               int row0, int B) {
    int r = row0 + blockIdx.x * blockDim.x + threadIdx.x;
    if (r >= B) return;
    float force = 0.5f * __sinf(6.283185307179586f * t[0]);
    const float* xr = x + (size_t)r * 5;
    float o[5];
    hb_row(xr[0], xr[1], xr[2], xr[3], xr[4], force, o);
    float* dr = drift + (size_t)r * 5;
    float* gr = diffu + (size_t)r * 5;
    dr[0] = o[0]; dr[1] = o[1]; dr[2] = o[2]; dr[3] = o[3]; dr[4] = o[4];
    gr[0] = 0.05f; gr[1] = 0.02f; gr[2] = 0.0f; gr[3] = 0.0f; gr[4] = 0.0f;
}

extern "C" void kernel_launch(void* const* d_in, const int* in_sizes, int n_in,
                              void* d_out, int out_size) {
    const float* t  = (const float*)d_in[0];   // [1]
    const float* x  = (const float*)d_in[1];   // [B*5]
    float* out      = (float*)d_out;
    int B           = in_sizes[1] / 5;
    int nf4         = in_sizes[1] / 4;         // assumes B*5 % 4 == 0 (B=8M)
    float4* drift4  = (float4*)out;
    float4* diffu4  = (float4*)(out + (size_t)out_size / 2);

    int nfull = nf4 / F4_PER_BLOCK;            // 7812 full blocks for B=8M
    int rows_covered = nfull * ROWS_PER_BLOCK; // 7,999,488
    int rem_rows = B - rows_covered;           // 512

    if (nfull > 0)
        hb_main_kernel<<<nfull, TPB>>>(t, (const float4*)x, drift4, diffu4);
    if (rem_rows > 0) {
        int tb = (rem_rows + 255) / 256;
        hb_tail_kernel<<<tb, 256>>>(t, x, (float*)drift4, (float*)diffu4,
                                    rows_covered, B);
    }
}

// round 7
// speedup vs baseline: 2.2591x; 1.0491x over previous
#include <cuda_runtime.h>

// HairBundle SDE drift + constant diffusion. Streaming, memory-bound.
// Floor: 160MB read + 320MB write = 480MB -> ~65us @ ~7.4TB/s achievable.
// R3: smem-staged coalesced, 88.6us. R4: overlap+stcs+no-pred, 77.9us
// (5.5us of which was the tail kernel at DRAM=0%).
// R5: single kernel, warp-granular work (160 f4 = 128 rows per warp),
//     warp-local smem staging with __syncwarp (no block barriers),
//     partial warps take a scalar fallback path.

#define TPB 256
#define WARPS_PER_BLOCK (TPB / 32)
#define F4_PER_WARP 160             // 32 lanes x 5 float4 = 128 rows

__device__ __forceinline__ void hb_row(float x_hb, float x_a, float p_m,
                                       float p_gs, float p_t, float force,
                                       float* __restrict__ o) {
    float z    = 4.0f * (x_hb - x_a);                 // (x_hb - x_a)/DELTA
    float p_o  = 1.0f / (1.0f + __expf(-z));          // sigmoid
    float f_gs = 0.75f * (x_hb - x_a - 0.5f * p_o);
    o[0] = -f_gs - 0.6f * x_hb + force;
    o[1] = 0.1f * (f_gs - 0.45f * x_a - 0.35f * (1.0f - 0.9f * p_m));
    o[2] = 1.2f * p_o * (1.0f - p_m)  - 0.8f * p_m;
    o[3] = 0.7f * p_o * (1.0f - p_gs) - 0.5f * p_gs;
    o[4] = 0.3f * p_o * (1.0f - p_t)  - 0.4f * p_t;
}

__global__ __launch_bounds__(TPB, 6)
void hb_kernel(const float* __restrict__ t,
               const float4* __restrict__ x4,
               float4* __restrict__ drift4,
               float4* __restrict__ diffu4,
               const float* __restrict__ xs,   // scalar view of x
               float* __restrict__ drs,        // scalar view of drift
               float* __restrict__ dfs,        // scalar view of diffusion
               int nf4, int B) {
    __shared__ float4 buf[WARPS_PER_BLOCK][F4_PER_WARP];
    const int lane = threadIdx.x & 31;
    const int w    = threadIdx.x >> 5;
    const int wg   = blockIdx.x * WARPS_PER_BLOCK + w;   // global warp id
    const int base = wg * F4_PER_WARP;                    // f4 offset (fits int)
    if (base >= nf4) return;

    const float force = 0.5f * __sinf(6.283185307179586f * t[0]);

    if (base + F4_PER_WARP <= nf4) {
        // ================= full warp: coalesced fast path =================
        // stage input: 5 x LDG.128, coalesced within warp
        float4 s0 = x4[base + lane +   0];
        float4 s1 = x4[base + lane +  32];
        float4 s2 = x4[base + lane +  64];
        float4 s3 = x4[base + lane +  96];
        float4 s4 = x4[base + lane + 128];

        // diffusion stores: dependency-free, fill the LDG latency window.
        // base % 5 == 0 (160 % 5 == 0), 32 % 5 == 2 -> pattern = (lane + 2k) % 5
        {
            int m = lane % 5;
            #pragma unroll
            for (int k = 0; k < 5; k++) {
                int p = m + 2 * k; p %= 5;
                float4 v = (p == 0) ? make_float4(0.05f, 0.02f, 0.0f,  0.0f)  :
                           (p == 1) ? make_float4(0.0f,  0.05f, 0.02f, 0.0f)  :
                           (p == 2) ? make_float4(0.0f,  0.0f,  0.05f, 0.02f) :
                           (p == 3) ? make_float4(0.0f,  0.0f,  0.0f,  0.05f) :
                                      make_float4(0.02f, 0.0f,  0.0f,  0.0f);
                __stcs(diffu4 + base + lane + k * 32, v);
            }
        }

        buf[w][lane +   0] = s0;
        buf[w][lane +  32] = s1;
        buf[w][lane +  64] = s2;
        buf[w][lane +  96] = s3;
        buf[w][lane + 128] = s4;
        __syncwarp();

        // compute 4 rows from smem (stride-5 reads), write back in place
        {
            const int i5 = lane * 5;
            float4 a = buf[w][i5 + 0];
            float4 b = buf[w][i5 + 1];
            float o0[5], o1[5];
            hb_row(a.x, a.y, a.z, a.w, b.x, force, o0);       // row 0
            float4 c = buf[w][i5 + 2];
            hb_row(b.y, b.z, b.w, c.x, c.y, force, o1);       // row 1
            buf[w][i5 + 0] = make_float4(o0[0], o0[1], o0[2], o0[3]);
            buf[w][i5 + 1] = make_float4(o0[4], o1[0], o1[1], o1[2]);
            float4 d = buf[w][i5 + 3];
            float o2[5];
            hb_row(c.z, c.w, d.x, d.y, d.z, force, o2);       // row 2
            buf[w][i5 + 2] = make_float4(o1[3], o1[4], o2[0], o2[1]);
            float4 e = buf[w][i5 + 4];
            float o3[5];
            hb_row(d.w, e.x, e.y, e.z, e.w, force, o3);       // row 3
            buf[w][i5 + 3] = make_float4(o2[2], o2[3], o2[4], o3[0]);
            buf[w][i5 + 4] = make_float4(o3[1], o3[2], o3[3], o3[4]);
        }
        __syncwarp();

        // stream drift out: coalesced STG.128, write-streaming
        __stcs(drift4 + base + lane +   0, buf[w][lane +   0]);
        __stcs(drift4 + base + lane +  32, buf[w][lane +  32]);
        __stcs(drift4 + base + lane +  64, buf[w][lane +  64]);
        __stcs(drift4 + base + lane +  96, buf[w][lane +  96]);
        __stcs(drift4 + base + lane + 128, buf[w][lane + 128]);
    } else {
        // ================= partial warp: scalar per-row fallback ==========
        int row0 = wg * 128;                      // 160 f4 = 128 rows per warp
        for (int r = row0 + lane; r < B; r += 32) {
            const float* xr = xs + (size_t)r * 5;
            float o[5];
            hb_row(xr[0], xr[1], xr[2], xr[3], xr[4], force, o);
            float* dr = drs + (size_t)r * 5;
            float* gr = dfs + (size_t)r * 5;
            dr[0] = o[0]; dr[1] = o[1]; dr[2] = o[2]; dr[3] = o[3]; dr[4] = o[4];
            gr[0] = 0.05f; gr[1] = 0.02f; gr[2] = 0.0f; gr[3] = 0.0f; gr[4] = 0.0f;
        }
    }
}

extern "C" void kernel_launch(void* const* d_in, const int* in_sizes, int n_in,
                              void* d_out, int out_size) {
    const float* t  = (const float*)d_in[0];   // [1]
    const float* x  = (const float*)d_in[1];   // [B*5]
    float* out      = (float*)d_out;
    int B           = in_sizes[1] / 5;
    int nf4         = in_sizes[1] / 4;         // B*5 % 4 == 0 for B=8M
    float* drift    = out;
    float* diffu    = out + (size_t)out_size / 2;

    int nwarps  = (nf4 + F4_PER_WARP - 1) / F4_PER_WARP;         // 62500
    int nblocks = (nwarps + WARPS_PER_BLOCK - 1) / WARPS_PER_BLOCK; // 7813

    hb_kernel<<<nblocks, TPB>>>(t, (const float4*)x,
                                (float4*)drift, (float4*)diffu,
                                x, drift, diffu, nf4, B);
}